// round 8
// baseline (speedup 1.0000x reference)
#include <cuda_runtime.h>
#include <math.h>

#define NB 32
#define NS 48000
#define L_CHUNK 64
#define NCH (NS / L_CHUNK)      /* 750 */
#define NPAIR (NCH / 2)         /* 375 */
#define PD 8                    /* out prefetch depth */
#define PLANE (NS * NB)

// 3 planes of float4, layout [n][b]:
//   plane0 = (sA_low, invL, sA_high, invH)
//   plane1 = (cw_mid, alA, alrA, invM)
//   plane2 = (sv, alpha_a*y_attack, 1-alpha_a, 0)
__device__ float4 g_p0[(size_t)PLANE];
__device__ float4 g_p1[(size_t)PLANE];
__device__ float4 g_p2[(size_t)PLANE];
// Per (chunk, lane) affine map: 30 floats, [c][b][30]
__device__ float g_maps[(size_t)NCH * NB * 30];
// Inclusive chunk-end states: 6 planes of [c][b]
__device__ float g_state[6 * (size_t)NCH * NB];

// shelf constants
#define CW_L  0.9994645875f     /* cos(2pi*250/48000) */
#define ALC_L 0.0231360485f     /* sin(w0_l)*sqrt(2)/2 */
#define CW_H  0.8660254038f     /* cos(pi/6) */
#define ALC_H 0.3535533906f     /* sin(pi/6)*sqrt(2)/2 */
#define KDB   0.0830482024f     /* log2(10)/40 */

// ---------------- fast approx helpers ----------------
__device__ __forceinline__ float f_tanh(float x) {
    float r; asm("tanh.approx.f32 %0, %1;" : "=f"(r) : "f"(x)); return r;
}
__device__ __forceinline__ float f_rcp(float x) {
    float r; asm("rcp.approx.f32 %0, %1;" : "=f"(r) : "f"(x)); return r;
}
__device__ __forceinline__ float f_ex2(float x) {
    float r; asm("ex2.approx.f32 %0, %1;" : "=f"(r) : "f"(x)); return r;
}
__device__ __forceinline__ float comp(const float4& v, int jj) {
    return jj == 0 ? v.x : jj == 1 ? v.y : jj == 2 ? v.z : v.w;
}

// ---------------------------------------------------------------------------
// Coefficient reconstruction: pure FMA/MUL (reciprocals precomputed).
// ---------------------------------------------------------------------------
__device__ __forceinline__ void make_coefs(const float4& pa, const float4& pb, float c[15])
{
    {   // low shelf: pa.x = sA, pa.y = 1/a0
        float sA = pa.x, inv = pa.y;
        float A  = sA * sA;
        float t  = 2.0f * sA * ALC_L;
        float ap = A + 1.0f, am = A - 1.0f;
        c[0] = A * (ap - am * CW_L + t) * inv;
        c[1] = 2.0f * A * (am - ap * CW_L) * inv;
        c[2] = A * (ap - am * CW_L - t) * inv;
        c[3] = -2.0f * (am + ap * CW_L) * inv;
        c[4] = (ap + am * CW_L - t) * inv;
    }
    {   // mid peaking: pb = (cw, alA, alrA, 1/a0)
        float cw = pb.x, alA = pb.y, alrA = pb.z, inv = pb.w;
        c[5] = (1.0f + alA) * inv;
        c[6] = -2.0f * cw * inv;
        c[7] = (1.0f - alA) * inv;
        c[8] = c[6];
        c[9] = (1.0f - alrA) * inv;
    }
    {   // high shelf: pa.z = sA, pa.w = 1/a0
        float sA = pa.z, inv = pa.w;
        float A  = sA * sA;
        float t  = 2.0f * sA * ALC_H;
        float ap = A + 1.0f, am = A - 1.0f;
        c[10] = A * (ap + am * CW_H + t) * inv;
        c[11] = -2.0f * A * (am + ap * CW_H) * inv;
        c[12] = A * (ap + am * CW_H - t) * inv;
        c[13] = 2.0f * (am - ap * CW_H) * inv;
        c[14] = (ap - am * CW_H - t) * inv;
    }
}

// ---------------------------------------------------------------------------
// Step primitives on coefficient array c[15].
// ---------------------------------------------------------------------------
__device__ __forceinline__ float stepF(const float c[15], float u[6], float v)
{
    float y1 = fmaf(c[0], v, u[0]);
    float a  = fmaf(c[1], v, fmaf(-c[3], y1, u[1]));
    float bb = fmaf(c[2], v, -c[4] * y1);
    float y2 = fmaf(c[5], y1, u[2]);
    float cc = fmaf(c[6], y1, fmaf(-c[8], y2, u[3]));
    float dd = fmaf(c[7], y1, -c[9] * y2);
    float y3 = fmaf(c[10], y2, u[4]);
    float ee = fmaf(c[11], y2, fmaf(-c[13], y3, u[5]));
    float ff = fmaf(c[12], y2, -c[14] * y3);
    u[0]=a; u[1]=bb; u[2]=cc; u[3]=dd; u[4]=ee; u[5]=ff;
    return y3;
}
__device__ __forceinline__ void stepM(const float c[15], float w[4])
{
    float y2 = w[0];
    float a  = fmaf(-c[8], y2, w[1]);
    float bb = -c[9] * y2;
    float y3 = fmaf(c[10], y2, w[2]);
    float cc = fmaf(c[11], y2, fmaf(-c[13], y3, w[3]));
    float dd = fmaf(c[12], y2, -c[14] * y3);
    w[0]=a; w[1]=bb; w[2]=cc; w[3]=dd;
}
__device__ __forceinline__ void stepH(const float c[15], float w[2])
{
    float y3 = w[0];
    float a  = fmaf(-c[13], y3, w[1]);
    float bb = -c[14] * y3;
    w[0]=a; w[1]=bb;
}

// ---------------------------------------------------------------------------
// Fused prep+map: one warp per 64-sample chunk, lane = batch row.
// Computes per-sample params from RAW inputs (lane-contiguous float4 reads),
// writes the 3 planes for out_kernel, and accumulates the chunk affine map.
// Envelope via per-lane smem x-window + |x| prefix sums.
// ---------------------------------------------------------------------------
__device__ __forceinline__ void do_sample(
        int n, int j, int jj, int lane,
        const float4& Lo, const float4& Mi, const float4& Fc, const float4& Qq,
        const float4& Hi, const float4& Al, const float4& Be, const float4& Aa,
        const float* rowx, const float* rowp,
        float u1[6], float u2[6], float u3[4], float u4[4],
        float u5[2], float u6[2], float dd[6])
{
    float lowdb = comp(Lo, jj), middb = comp(Mi, jj);
    float fc    = comp(Fc, jj), Qv    = comp(Qq, jj);
    float highdb= comp(Hi, jj), alv   = comp(Al, jj);
    float bev   = comp(Be, jj), aav   = comp(Aa, jj);

    float xv  = rowx[j + 8];
    float env = (rowp[j + 16] - rowp[j + 1]) * (1.0f / 15.0f);
    float xa  = fabsf(xv);
    float gate = fmaf(0.5f, f_tanh(4.0f * (xa - env)), 0.5f);
    float av = gate * xv;
    float sv = (1.0f - gate) * xv;
    float ya = f_tanh(fmaf(alv, av, bev)) - f_tanh(bev);

    float sA_l = f_ex2(lowdb * (0.5f * KDB));
    float sA_h = f_ex2(highdb * (0.5f * KDB));
    float invL, invH;
    {
        float A = sA_l * sA_l, t = 2.0f * sA_l * ALC_L;
        invL = f_rcp((A + 1.0f) + (A - 1.0f) * CW_L + t);
    }
    {
        float A = sA_h * sA_h, t = 2.0f * sA_h * ALC_H;
        invH = f_rcp((A + 1.0f) - (A - 1.0f) * CW_H + t);
    }
    float A_m = f_ex2(middb * KDB);
    float w0  = fc * 1.30899693e-4f;     // 2*pi/48000
    float sw = __sinf(w0), cw = __cosf(w0);
    float alq  = sw * 0.5f * f_rcp(Qv);
    float alA  = alq * A_m;
    float alrA = alq * f_rcp(A_m);
    float invM = f_rcp(1.0f + alrA);

    float4 pa = make_float4(sA_l, invL, sA_h, invH);
    float4 pb = make_float4(cw, alA, alrA, invM);
    size_t o = (size_t)n * NB + lane;
    g_p0[o] = pa;
    g_p1[o] = pb;
    g_p2[o] = make_float4(sv, aav * ya, 1.0f - aav, 0.0f);

    float cf[15];
    make_coefs(pa, pb, cf);
    stepF(cf, u1, 0.0f);
    stepF(cf, u2, 0.0f);
    stepM(cf, u3);
    stepM(cf, u4);
    stepH(cf, u5);
    stepH(cf, u6);
    stepF(cf, dd, sv);
}

__global__ void __launch_bounds__(32) mapfuse_kernel(
        const float* __restrict__ x,
        const float* __restrict__ alpha,
        const float* __restrict__ beta,
        const float* __restrict__ low_db,
        const float* __restrict__ mid_db,
        const float* __restrict__ mid_fc,
        const float* __restrict__ mid_Q,
        const float* __restrict__ high_db,
        const float* __restrict__ alpha_a)
{
    __shared__ float sx[32 * 83];    // x window  x[n0-8 .. n0+71], row stride 83
    __shared__ float sp[32 * 83];    // prefix sums of |x| (P[0..80])

    const int c = blockIdx.x;
    const int lane = threadIdx.x;
    const int n0 = c * L_CHUNK;
    const float* xb = x + (size_t)lane * NS;

    // ---- load x window + build |x| prefix (per-lane private rows) ----
    float* rowx = sx + lane * 83;
    float* rowp = sp + lane * 83;
    {
        float acc = 0.0f;
        rowp[0] = 0.0f;
        #pragma unroll
        for (int k4 = 0; k4 < 20; ++k4) {
            int g = n0 - 8 + 4 * k4;
            float4 v;
            if (g >= 0 && g + 3 < NS) {
                v = *(const float4*)(xb + g);
            } else {
                v.x = (g + 0 >= 0 && g + 0 < NS) ? xb[g + 0] : 0.0f;
                v.y = (g + 1 >= 0 && g + 1 < NS) ? xb[g + 1] : 0.0f;
                v.z = (g + 2 >= 0 && g + 2 < NS) ? xb[g + 2] : 0.0f;
                v.w = (g + 3 >= 0 && g + 3 < NS) ? xb[g + 3] : 0.0f;
            }
            rowx[4 * k4 + 0] = v.x;
            rowx[4 * k4 + 1] = v.y;
            rowx[4 * k4 + 2] = v.z;
            rowx[4 * k4 + 3] = v.w;
            acc += fabsf(v.x); rowp[4 * k4 + 1] = acc;
            acc += fabsf(v.y); rowp[4 * k4 + 2] = acc;
            acc += fabsf(v.z); rowp[4 * k4 + 3] = acc;
            acc += fabsf(v.w); rowp[4 * k4 + 4] = acc;
        }
    }

    // ---- affine-map accumulators ----
    float u1[6] = {1,0,0,0,0,0};
    float u2[6] = {0,1,0,0,0,0};
    float u3[4] = {1,0,0,0};
    float u4[4] = {0,1,0,0};
    float u5[2] = {1,0};
    float u6[2] = {0,1};
    float dd[6] = {0,0,0,0,0,0};

    const size_t base = (size_t)lane * NS + n0;
    #define LD4(arr, g) (*(const float4*)((arr) + base + 4 * (g)))

    // double-buffered group pipeline (16 groups of 4 samples)
    float4 L0 = LD4(low_db, 0),  M0 = LD4(mid_db, 0),  F0 = LD4(mid_fc, 0);
    float4 Q0 = LD4(mid_Q, 0),   H0 = LD4(high_db, 0);
    float4 A0 = LD4(alpha, 0),   B0 = LD4(beta, 0),    Aa0 = LD4(alpha_a, 0);
    float4 L1, M1, F1, Q1, H1, A1, B1, Aa1;

    for (int g2 = 0; g2 < 8; ++g2) {
        const int ga = 2 * g2, gb = 2 * g2 + 1;
        // prefetch group gb into slot 1
        L1 = LD4(low_db, gb);  M1 = LD4(mid_db, gb);  F1 = LD4(mid_fc, gb);
        Q1 = LD4(mid_Q, gb);   H1 = LD4(high_db, gb);
        A1 = LD4(alpha, gb);   B1 = LD4(beta, gb);    Aa1 = LD4(alpha_a, gb);
        #pragma unroll
        for (int jj = 0; jj < 4; ++jj) {
            int j = 4 * ga + jj;
            do_sample(n0 + j, j, jj, lane, L0, M0, F0, Q0, H0, A0, B0, Aa0,
                      rowx, rowp, u1, u2, u3, u4, u5, u6, dd);
        }
        // prefetch group ga+2 into slot 0
        if (g2 < 7) {
            int gn = ga + 2;
            L0 = LD4(low_db, gn);  M0 = LD4(mid_db, gn);  F0 = LD4(mid_fc, gn);
            Q0 = LD4(mid_Q, gn);   H0 = LD4(high_db, gn);
            A0 = LD4(alpha, gn);   B0 = LD4(beta, gn);    Aa0 = LD4(alpha_a, gn);
        }
        #pragma unroll
        for (int jj = 0; jj < 4; ++jj) {
            int j = 4 * gb + jj;
            do_sample(n0 + j, j, jj, lane, L1, M1, F1, Q1, H1, A1, B1, Aa1,
                      rowx, rowp, u1, u2, u3, u4, u5, u6, dd);
        }
    }
    #undef LD4

    float* rec = g_maps + (size_t)(c * NB + lane) * 30;
    #pragma unroll
    for (int k = 0; k < 6; ++k) rec[k]      = u1[k];
    #pragma unroll
    for (int k = 0; k < 6; ++k) rec[6 + k]  = u2[k];
    #pragma unroll
    for (int k = 0; k < 4; ++k) rec[12 + k] = u3[k];
    #pragma unroll
    for (int k = 0; k < 4; ++k) rec[16 + k] = u4[k];
    rec[20] = u5[0]; rec[21] = u5[1];
    rec[22] = u6[0]; rec[23] = u6[1];
    #pragma unroll
    for (int k = 0; k < 6; ++k) rec[24 + k] = dd[k];
}

// ---------------------------------------------------------------------------
// Map compose helpers (block-lower-triangular sparsity).
// ---------------------------------------------------------------------------
__device__ __forceinline__ void bmv_full(const float* B, const float* w, float* r)
{
    r[0] = w[0]*B[0] + w[1]*B[6];
    r[1] = w[0]*B[1] + w[1]*B[7];
    r[2] = w[0]*B[2] + w[1]*B[8]  + w[2]*B[12] + w[3]*B[16];
    r[3] = w[0]*B[3] + w[1]*B[9]  + w[2]*B[13] + w[3]*B[17];
    r[4] = w[0]*B[4] + w[1]*B[10] + w[2]*B[14] + w[3]*B[18] + w[4]*B[20] + w[5]*B[22];
    r[5] = w[0]*B[5] + w[1]*B[11] + w[2]*B[15] + w[3]*B[19] + w[4]*B[21] + w[5]*B[23];
}
__device__ __forceinline__ void bmv_mid(const float* B, const float* w, float* r)
{
    r[0] = w[0]*B[12] + w[1]*B[16];
    r[1] = w[0]*B[13] + w[1]*B[17];
    r[2] = w[0]*B[14] + w[1]*B[18] + w[2]*B[20] + w[3]*B[22];
    r[3] = w[0]*B[15] + w[1]*B[19] + w[2]*B[21] + w[3]*B[23];
}
__device__ __forceinline__ void bmv_high(const float* B, const float* w, float* r)
{
    r[0] = w[0]*B[20] + w[1]*B[22];
    r[1] = w[0]*B[21] + w[1]*B[23];
}
// C = B after A  (A applied first)
__device__ __forceinline__ void compose(const float* A, const float* B, float* C)
{
    bmv_full(B, A + 0,  C + 0);
    bmv_full(B, A + 6,  C + 6);
    bmv_mid (B, A + 12, C + 12);
    bmv_mid (B, A + 16, C + 16);
    bmv_high(B, A + 20, C + 20);
    bmv_high(B, A + 22, C + 22);
    float t6[6];
    bmv_full(B, A + 24, t6);
    #pragma unroll
    for (int k = 0; k < 6; ++k) C[24 + k] = t6[k] + B[24 + k];
}

// ---------------------------------------------------------------------------
// Scan: one block per batch lane. Pair-compose in registers, Hillis-Steele
// over 375 pairs in smem, emit both chunk-end states.
// ---------------------------------------------------------------------------
__global__ void __launch_bounds__(384) scan_kernel()
{
    __shared__ float sm[NPAIR * 30];    // 45000 B
    const int t = threadIdx.x;
    const int b = blockIdx.x;
    const bool on = (t < NPAIR);

    float A[30];
    if (on) {
        const float* srcA = g_maps + (size_t)((2 * t)     * NB + b) * 30;
        const float* srcB = g_maps + (size_t)((2 * t + 1) * NB + b) * 30;
        float Bm[30], P[30];
        #pragma unroll
        for (int k = 0; k < 30; ++k) A[k]  = srcA[k];
        #pragma unroll
        for (int k = 0; k < 30; ++k) Bm[k] = srcB[k];
        compose(A, Bm, P);
        #pragma unroll
        for (int k = 0; k < 30; ++k) sm[t * 30 + k] = P[k];
    }
    __syncthreads();

    for (int off = 1; off < NPAIR; off <<= 1) {
        float Ap[30], Bp[30];
        const bool act = on && (t >= off);
        if (act) {
            #pragma unroll
            for (int k = 0; k < 30; ++k) Ap[k] = sm[(t - off) * 30 + k];
            #pragma unroll
            for (int k = 0; k < 30; ++k) Bp[k] = sm[t * 30 + k];
        }
        __syncthreads();
        if (act) {
            float C[30];
            compose(Ap, Bp, C);
            #pragma unroll
            for (int k = 0; k < 30; ++k) sm[t * 30 + k] = C[k];
        }
        __syncthreads();
    }

    if (on) {
        #pragma unroll
        for (int k = 0; k < 6; ++k)
            g_state[(size_t)k * (NCH * NB) + (2 * t + 1) * NB + b] = sm[t * 30 + 24 + k];
        float se[6];
        if (t == 0) {
            #pragma unroll
            for (int k = 0; k < 6; ++k) se[k] = A[24 + k];
        } else {
            float w[6];
            #pragma unroll
            for (int k = 0; k < 6; ++k) w[k] = sm[(t - 1) * 30 + 24 + k];
            bmv_full(A, w, se);
            #pragma unroll
            for (int k = 0; k < 6; ++k) se[k] += A[24 + k];
        }
        #pragma unroll
        for (int k = 0; k < 6; ++k)
            g_state[(size_t)k * (NCH * NB) + (2 * t) * NB + b] = se[k];
    }
}

// ---------------------------------------------------------------------------
// Pass 2: final IIR per 64-sample chunk with exact initial state.
// ---------------------------------------------------------------------------
__global__ void __launch_bounds__(32) out_kernel(float* __restrict__ out)
{
    const int c = blockIdx.x;
    const int lane = threadIdx.x;
    const int n0 = c * L_CHUNK;

    const float4* __restrict__ p0 = g_p0;
    const float4* __restrict__ p1 = g_p1;
    const float4* __restrict__ p2 = g_p2;

    float s[6] = {0,0,0,0,0,0};
    if (c > 0) {
        #pragma unroll
        for (int k = 0; k < 6; ++k)
            s[k] = g_state[(size_t)k * (NCH * NB) + (c - 1) * NB + lane];
    }

    float4 qa[PD], qb[PD], qc[PD];
    #pragma unroll
    for (int d = 0; d < PD; ++d) {
        int ofs = (n0 + d) * NB + lane;
        qa[d] = p0[ofs]; qb[d] = p1[ofs]; qc[d] = p2[ofs];
    }

    __shared__ float buf[32 * 33];

    for (int t = 0; t < L_CHUNK / 32; ++t) {
        const int nb_ = n0 + (t << 5);
        #pragma unroll
        for (int j = 0; j < 32; ++j) {
            const int slot = j & (PD - 1);
            float4 a = qa[slot], b = qb[slot], m = qc[slot];
            int nf = nb_ + j + PD;
            if (nf > NS - 1) nf = NS - 1;
            int ofs = nf * NB + lane;
            qa[slot] = p0[ofs]; qb[slot] = p1[ofs]; qc[slot] = p2[ofs];

            float cf[15];
            make_coefs(a, b, cf);
            float ys = stepF(cf, s, m.x);
            buf[lane * 33 + j] = fmaf(m.z, ys, m.y);
        }
        __syncwarp();
        const int nw = nb_ + lane;
        #pragma unroll
        for (int b2 = 0; b2 < 32; ++b2)
            out[b2 * NS + nw] = buf[b2 * 33 + lane];
        __syncwarp();
    }
}

extern "C" void kernel_launch(void* const* d_in, const int* in_sizes, int n_in,
                              void* d_out, int out_size)
{
    const float* x       = (const float*)d_in[0];
    const float* alpha   = (const float*)d_in[1];
    const float* beta    = (const float*)d_in[2];
    const float* low_db  = (const float*)d_in[3];
    const float* mid_db  = (const float*)d_in[4];
    const float* mid_fc  = (const float*)d_in[5];
    const float* mid_Q   = (const float*)d_in[6];
    const float* high_db = (const float*)d_in[7];
    const float* alpha_a = (const float*)d_in[8];
    float* out = (float*)d_out;

    mapfuse_kernel<<<NCH, 32>>>(x, alpha, beta, low_db, mid_db, mid_fc,
                                mid_Q, high_db, alpha_a);
    scan_kernel<<<NB, 384>>>();
    out_kernel<<<NCH, 32>>>(out);
}